// round 5
// baseline (speedup 1.0000x reference)
#include <cuda_runtime.h>
#include <math.h>

// Problem constants (fixed shapes from setup_inputs)
#define D      512
#define BQ     4096
#define NMEM   32768
#define TOPN   10
#define NHEADS 8

// ---------------------------------------------------------------------------
// Device scratch (static __device__ arrays; no allocation anywhere)
// ---------------------------------------------------------------------------
__device__ float g_s[(size_t)BQ * NMEM];      // 512 MB distance scratch
__device__ float g_mnorm[NMEM];
__device__ int   g_I[BQ * TOPN];
__device__ float g_qh[(size_t)BQ * D];
__device__ float g_kh[(size_t)BQ * TOPN * D];
__device__ float g_vh[(size_t)BQ * TOPN * D];
__device__ float g_ctx[(size_t)BQ * D];
__device__ float g_y[(size_t)BQ * D];
__device__ float g_x[(size_t)BQ * D];
__device__ float g_h1[(size_t)BQ * D];
__device__ float g_y2[(size_t)BQ * D];

// ---------------------------------------------------------------------------
// ||M_j||^2 per memory row. 8 rows per block, one warp per row.
// ---------------------------------------------------------------------------
__global__ void mnorm_kernel(const float* __restrict__ M, float* __restrict__ mn)
{
    int w = threadIdx.x >> 5, lane = threadIdx.x & 31;
    int row = blockIdx.x * 8 + w;
    const float* mr = M + (size_t)row * D;
    float s = 0.f;
#pragma unroll
    for (int i = 0; i < D / 32; i++) { float v = mr[lane + i * 32]; s += v * v; }
#pragma unroll
    for (int o = 16; o; o >>= 1) s += __shfl_xor_sync(0xFFFFFFFFu, s, o);
    if (lane == 0) mn[row] = s;
}

// ---------------------------------------------------------------------------
// Generic fp32 GEMM (NT): C[m,n] = act( alpha * sum_k A[m,k]*B[n,k]
//                                       + bias[n] + resid[m,n] )
// Optional row gather on A via gidx. Tile 128x128, BK=16, 8x8 per thread.
// Grid: (N/128, M/128), 256 threads. All dims divide tiles exactly here.
// ---------------------------------------------------------------------------
__global__ __launch_bounds__(256, 2)
void gemm_nt_kernel(const float* __restrict__ A,
                    const float* __restrict__ Bm,
                    const float* __restrict__ bias,
                    const float* __restrict__ resid,
                    const int*   __restrict__ gidx,
                    float* __restrict__ C,
                    int N, int K, float alpha, int leaky)
{
    __shared__ float As[16][129];
    __shared__ float Bs[16][129];
    const int tid = threadIdx.x;
    const int bx = blockIdx.x, by = blockIdx.y;
    const int rbase = tid >> 4;   // 0..15 (M sub-row)
    const int cbase = tid & 15;   // 0..15 (N sub-col)

    float acc[8][8];
#pragma unroll
    for (int i = 0; i < 8; i++)
#pragma unroll
        for (int j = 0; j < 8; j++) acc[i][j] = 0.f;

    for (int k0 = 0; k0 < K; k0 += 16) {
        // 512 float4 loads for each tile; 2 (A) + 2 (B) per thread
        for (int l = tid; l < 512; l += 256) {
            int r = l >> 2, c4 = l & 3;
            int arow = by * 128 + r;
            if (gidx) arow = gidx[arow];
            float4 av = *(const float4*)(A + (size_t)arow * K + k0 + c4 * 4);
            As[c4 * 4 + 0][r] = av.x; As[c4 * 4 + 1][r] = av.y;
            As[c4 * 4 + 2][r] = av.z; As[c4 * 4 + 3][r] = av.w;
            int brow = bx * 128 + r;
            float4 bv = *(const float4*)(Bm + (size_t)brow * K + k0 + c4 * 4);
            Bs[c4 * 4 + 0][r] = bv.x; Bs[c4 * 4 + 1][r] = bv.y;
            Bs[c4 * 4 + 2][r] = bv.z; Bs[c4 * 4 + 3][r] = bv.w;
        }
        __syncthreads();
#pragma unroll
        for (int kk = 0; kk < 16; kk++) {
            float a[8], b[8];
#pragma unroll
            for (int i = 0; i < 8; i++) a[i] = As[kk][rbase + i * 16];
#pragma unroll
            for (int j = 0; j < 8; j++) b[j] = Bs[kk][cbase + j * 16];
#pragma unroll
            for (int i = 0; i < 8; i++)
#pragma unroll
                for (int j = 0; j < 8; j++)
                    acc[i][j] = fmaf(a[i], b[j], acc[i][j]);
        }
        __syncthreads();
    }

#pragma unroll
    for (int i = 0; i < 8; i++) {
        int row = by * 128 + rbase + i * 16;
#pragma unroll
        for (int j = 0; j < 8; j++) {
            int col = bx * 128 + cbase + j * 16;
            float v = alpha * acc[i][j];
            if (bias)  v += bias[col];
            if (resid) v += resid[(size_t)row * N + col];
            if (leaky) v = v > 0.f ? v : 0.01f * v;
            C[(size_t)row * N + col] = v;
        }
    }
}

// ---------------------------------------------------------------------------
// Per-row top-10 smallest over s[row, 0..NMEM). One block (256 thr) per row.
// ---------------------------------------------------------------------------
__device__ __forceinline__ void tk_insert(float v, int idx, float* bv, int* bi)
{
    if (v < bv[TOPN - 1]) {
        float cv = v; int ci = idx;
#pragma unroll
        for (int t = 0; t < TOPN; t++) {
            if (cv < bv[t]) {
                float tv = bv[t]; int ti = bi[t];
                bv[t] = cv; bi[t] = ci;
                cv = tv; ci = ti;
            }
        }
    }
}

__global__ void topk_kernel(const float* __restrict__ s, int* __restrict__ I)
{
    int row = blockIdx.x, tid = threadIdx.x;
    const float* sr = s + (size_t)row * NMEM;
    float bv[TOPN]; int bi[TOPN];
#pragma unroll
    for (int t = 0; t < TOPN; t++) { bv[t] = 3.402823466e38f; bi[t] = 0; }

    for (int j = tid; j < NMEM; j += 256) tk_insert(sr[j], j, bv, bi);

    __shared__ float sv[256 * TOPN];
    __shared__ int   si[256 * TOPN];
#pragma unroll
    for (int t = 0; t < TOPN; t++) { sv[tid * TOPN + t] = bv[t]; si[tid * TOPN + t] = bi[t]; }
    __syncthreads();

    if (tid < 32) {
        for (int k = 1; k < 8; k++) {
            int base = (tid + 32 * k) * TOPN;
            for (int t = 0; t < TOPN; t++) tk_insert(sv[base + t], si[base + t], bv, bi);
        }
#pragma unroll
        for (int t = 0; t < TOPN; t++) { sv[tid * TOPN + t] = bv[t]; si[tid * TOPN + t] = bi[t]; }
    }
    __syncthreads();

    if (tid == 0) {
        for (int k = 1; k < 32; k++) {
            int base = k * TOPN;
            for (int t = 0; t < TOPN; t++) tk_insert(sv[base + t], si[base + t], bv, bi);
        }
#pragma unroll
        for (int t = 0; t < TOPN; t++) I[row * TOPN + t] = bi[t];
    }
}

// ---------------------------------------------------------------------------
// Attention: query seq-len 1, 10 keys, 8 heads x hd=64. One block per b,
// one warp per head; lane covers d and d+32.
// ---------------------------------------------------------------------------
__global__ void attn_kernel(const float* __restrict__ qh,
                            const float* __restrict__ kh,
                            const float* __restrict__ vh,
                            float* __restrict__ ctx)
{
    int b = blockIdx.x;
    int h = threadIdx.x >> 5, lane = threadIdx.x & 31;
    const float* qp = qh + (size_t)b * D + h * 64;
    float q0 = qp[lane], q1 = qp[lane + 32];

    float sc[TOPN];
#pragma unroll
    for (int n = 0; n < TOPN; n++) {
        const float* kp = kh + ((size_t)b * TOPN + n) * D + h * 64;
        float p = q0 * kp[lane] + q1 * kp[lane + 32];
#pragma unroll
        for (int o = 16; o; o >>= 1) p += __shfl_xor_sync(0xFFFFFFFFu, p, o);
        sc[n] = p * 0.125f;  // 1/sqrt(64)
    }
    float mx = sc[0];
#pragma unroll
    for (int n = 1; n < TOPN; n++) mx = fmaxf(mx, sc[n]);
    float den = 0.f;
#pragma unroll
    for (int n = 0; n < TOPN; n++) { sc[n] = expf(sc[n] - mx); den += sc[n]; }
    float inv = 1.f / den;

    float c0 = 0.f, c1 = 0.f;
#pragma unroll
    for (int n = 0; n < TOPN; n++) {
        const float* vp = vh + ((size_t)b * TOPN + n) * D + h * 64;
        float a = sc[n] * inv;
        c0 = fmaf(a, vp[lane], c0);
        c1 = fmaf(a, vp[lane + 32], c1);
    }
    ctx[(size_t)b * D + h * 64 + lane]      = c0;
    ctx[(size_t)b * D + h * 64 + lane + 32] = c1;
}

// ---------------------------------------------------------------------------
// LayerNorm over last dim (512). One block (128 thr) per row.
// ---------------------------------------------------------------------------
__global__ void ln_kernel(const float* __restrict__ y,
                          const float* __restrict__ g,
                          const float* __restrict__ b,
                          float* __restrict__ out)
{
    int row = blockIdx.x, tid = threadIdx.x;
    const float* yr = y + (size_t)row * D;
    float v[4];
#pragma unroll
    for (int i = 0; i < 4; i++) v[i] = yr[tid + i * 128];

    __shared__ float red[4];
    float s = v[0] + v[1] + v[2] + v[3];
#pragma unroll
    for (int o = 16; o; o >>= 1) s += __shfl_xor_sync(0xFFFFFFFFu, s, o);
    if ((tid & 31) == 0) red[tid >> 5] = s;
    __syncthreads();
    float mu = (red[0] + red[1] + red[2] + red[3]) * (1.f / D);

    float s2 = 0.f;
#pragma unroll
    for (int i = 0; i < 4; i++) { float d = v[i] - mu; s2 += d * d; }
#pragma unroll
    for (int o = 16; o; o >>= 1) s2 += __shfl_xor_sync(0xFFFFFFFFu, s2, o);
    __syncthreads();  // everyone has read red before overwrite
    if ((tid & 31) == 0) red[tid >> 5] = s2;
    __syncthreads();
    float var = (red[0] + red[1] + red[2] + red[3]) * (1.f / D);
    float invs = rsqrtf(var + 1e-5f);

#pragma unroll
    for (int i = 0; i < 4; i++) {
        int c = tid + i * 128;
        out[(size_t)row * D + c] = (v[i] - mu) * invs * g[c] + b[c];
    }
}

// ---------------------------------------------------------------------------
// Host launcher
// ---------------------------------------------------------------------------
extern "C" void kernel_launch(void* const* d_in, const int* in_sizes, int n_in,
                              void* d_out, int out_size)
{
    (void)n_in; (void)out_size;
    const float* visit = (const float*)d_in[0];
    const float* Epat  = (const float*)d_in[1];
    const float* Emed  = (const float*)d_in[2];

    const float *Wq, *bq, *Wk, *bk, *Wv, *bv;
    if (in_sizes[4] == D) {
        // signature order: Wq, bq, Wk, bk, Wv, bv
        Wq = (const float*)d_in[3]; bq = (const float*)d_in[4];
        Wk = (const float*)d_in[5]; bk = (const float*)d_in[6];
        Wv = (const float*)d_in[7]; bv = (const float*)d_in[8];
    } else {
        // dict order: Wq, Wk, Wv, bq, bk, bv
        Wq = (const float*)d_in[3]; Wk = (const float*)d_in[4]; Wv = (const float*)d_in[5];
        bq = (const float*)d_in[6]; bk = (const float*)d_in[7]; bv = (const float*)d_in[8];
    }
    const float* Wo  = (const float*)d_in[9];
    const float* bo  = (const float*)d_in[10];
    const float* W1  = (const float*)d_in[11];
    const float* b1  = (const float*)d_in[12];
    const float* W2  = (const float*)d_in[13];
    const float* b2  = (const float*)d_in[14];
    const float* g1  = (const float*)d_in[15];
    const float* be1 = (const float*)d_in[16];
    const float* g2  = (const float*)d_in[17];
    const float* be2 = (const float*)d_in[18];

    float *s, *mn, *qh, *kh, *vh, *ctx, *y, *x, *h1, *y2;
    int* I;
    cudaGetSymbolAddress((void**)&s,   g_s);
    cudaGetSymbolAddress((void**)&mn,  g_mnorm);
    cudaGetSymbolAddress((void**)&I,   g_I);
    cudaGetSymbolAddress((void**)&qh,  g_qh);
    cudaGetSymbolAddress((void**)&kh,  g_kh);
    cudaGetSymbolAddress((void**)&vh,  g_vh);
    cudaGetSymbolAddress((void**)&ctx, g_ctx);
    cudaGetSymbolAddress((void**)&y,   g_y);
    cudaGetSymbolAddress((void**)&x,   g_x);
    cudaGetSymbolAddress((void**)&h1,  g_h1);
    cudaGetSymbolAddress((void**)&y2,  g_y2);

    // 1) ||M||^2
    mnorm_kernel<<<NMEM / 8, 256>>>(Epat, mn);

    // 2) s = ||M||^2 - 2 * Q @ M^T   [BQ, NMEM]
    gemm_nt_kernel<<<dim3(NMEM / 128, BQ / 128), 256>>>(
        visit, Epat, mn, nullptr, nullptr, s, NMEM, D, -2.f, 0);

    // 3) top-10 smallest per row -> indices
    topk_kernel<<<BQ, 256>>>(s, I);

    // 4) projections
    gemm_nt_kernel<<<dim3(D / 128, BQ / 128), 256>>>(
        visit, Wq, bq, nullptr, nullptr, qh, D, D, 1.f, 0);
    gemm_nt_kernel<<<dim3(D / 128, (BQ * TOPN) / 128), 256>>>(
        Epat, Wk, bk, nullptr, I, kh, D, D, 1.f, 0);
    gemm_nt_kernel<<<dim3(D / 128, (BQ * TOPN) / 128), 256>>>(
        Emed, Wv, bv, nullptr, I, vh, D, D, 1.f, 0);

    // 5) attention (seq-len 1 x 10 keys)
    attn_kernel<<<BQ, 256>>>(qh, kh, vh, ctx);

    // 6) y = ctx @ Wo^T + bo + visit ; x = LN1(y)
    gemm_nt_kernel<<<dim3(D / 128, BQ / 128), 256>>>(
        ctx, Wo, bo, visit, nullptr, y, D, D, 1.f, 0);
    ln_kernel<<<BQ, 128>>>(y, g1, be1, x);

    // 7) FFN: h1 = leaky(x @ W1^T + b1) ; y2 = h1 @ W2^T + b2 + x ; out = LN2(y2)
    gemm_nt_kernel<<<dim3(D / 128, BQ / 128), 256>>>(
        x, W1, b1, nullptr, nullptr, h1, D, D, 1.f, 1);
    gemm_nt_kernel<<<dim3(D / 128, BQ / 128), 256>>>(
        h1, W2, b2, x, nullptr, y2, D, D, 1.f, 0);
    ln_kernel<<<BQ, 128>>>(y2, g2, be2, (float*)d_out);
}

// round 15
// speedup vs baseline: 2.7621x; 2.7621x over previous
#include <cuda_runtime.h>
#include <cuda_bf16.h>
#include <stdint.h>
#include <math.h>

// Problem constants (fixed shapes from setup_inputs)
#define D      512
#define BQ     4096
#define NMEM   32768
#define TOPN   10
#define TOPC   16     // candidate count for approx stage
#define NHEADS 8

// ---------------------------------------------------------------------------
// Device scratch (static __device__ arrays; no allocation anywhere)
// ---------------------------------------------------------------------------
__device__ float g_s[(size_t)BQ * NMEM];      // 512 MB approx-distance scratch
__device__ float g_mnorm[NMEM];
__device__ int   g_C[BQ * TOPC];              // top-16 candidates (approx)
__device__ int   g_I[BQ * TOPN];              // exact top-10
__device__ __nv_bfloat16 g_qb[(size_t)BQ * D];
__device__ __nv_bfloat16 g_mb[(size_t)NMEM * D];
__device__ float g_qh[(size_t)BQ * D];
__device__ float g_kh[(size_t)BQ * TOPN * D];
__device__ float g_vh[(size_t)BQ * TOPN * D];
__device__ float g_ctx[(size_t)BQ * D];
__device__ float g_y[(size_t)BQ * D];
__device__ float g_x[(size_t)BQ * D];
__device__ float g_h1[(size_t)BQ * D];
__device__ float g_y2[(size_t)BQ * D];

// ---------------------------------------------------------------------------
// fp32 -> bf16 conversion (n multiple of 4)
// ---------------------------------------------------------------------------
__global__ void cvt_bf16_kernel(const float* __restrict__ in,
                                __nv_bfloat16* __restrict__ out, int n4)
{
    int i = blockIdx.x * blockDim.x + threadIdx.x;
    if (i >= n4) return;
    float4 v = ((const float4*)in)[i];
    __nv_bfloat162 p0 = __floats2bfloat162_rn(v.x, v.y);
    __nv_bfloat162 p1 = __floats2bfloat162_rn(v.z, v.w);
    ((__nv_bfloat162*)out)[i * 2 + 0] = p0;
    ((__nv_bfloat162*)out)[i * 2 + 1] = p1;
}

// ---------------------------------------------------------------------------
// ||M_j||^2 per memory row (fp32, exact). 8 rows per block, one warp per row.
// ---------------------------------------------------------------------------
__global__ void mnorm_kernel(const float* __restrict__ M, float* __restrict__ mn)
{
    int w = threadIdx.x >> 5, lane = threadIdx.x & 31;
    int row = blockIdx.x * 8 + w;
    const float* mr = M + (size_t)row * D;
    float s = 0.f;
#pragma unroll
    for (int i = 0; i < D / 32; i++) { float v = mr[lane + i * 32]; s += v * v; }
#pragma unroll
    for (int o = 16; o; o >>= 1) s += __shfl_xor_sync(0xFFFFFFFFu, s, o);
    if (lane == 0) mn[row] = s;
}

// ---------------------------------------------------------------------------
// bf16 tensor-core distance kernel:
//   S[m,n] = mnorm[n] - 2 * sum_k Qb[m,k]*Mb[n,k]     (fp32 accumulate)
// Tile 128x128xK, BK=64 bf16, 8 warps (2x4), warp tile 64x32.
// SW128 swizzled smem + ldmatrix + mma.sync.m16n8k16.
// ---------------------------------------------------------------------------
__global__ __launch_bounds__(256, 2)
void dist_mma_kernel(const __nv_bfloat16* __restrict__ Qb,
                     const __nv_bfloat16* __restrict__ Mb,
                     const float* __restrict__ mn,
                     float* __restrict__ S)
{
    __shared__ __nv_bfloat16 As[128 * 64];
    __shared__ __nv_bfloat16 Bs[128 * 64];
    const int tid  = threadIdx.x;
    const int lane = tid & 31;
    const int warp = tid >> 5;
    const int wm = warp >> 2;   // 0..1  (64-row block)
    const int wn = warp & 3;    // 0..3  (32-col block)
    const int bx = blockIdx.x, by = blockIdx.y;

    float acc[4][4][4];
#pragma unroll
    for (int i = 0; i < 4; i++)
#pragma unroll
        for (int j = 0; j < 4; j++)
#pragma unroll
            for (int k = 0; k < 4; k++) acc[i][j][k] = 0.f;

    unsigned aBase = (unsigned)__cvta_generic_to_shared(As);
    unsigned bBase = (unsigned)__cvta_generic_to_shared(Bs);
    const __nv_bfloat16* Ag = Qb + (size_t)(by * 128) * D;
    const __nv_bfloat16* Bg = Mb + (size_t)(bx * 128) * D;

    for (int k0 = 0; k0 < D; k0 += 64) {
        // fill both 128x64 tiles: 1024 16-byte chunks each -> 4 per thread
#pragma unroll
        for (int l = tid; l < 1024; l += 256) {
            int r = l >> 3, c = l & 7;
            int sw = r * 128 + ((c ^ (r & 7)) << 4);   // SW128 swizzle, 128B rows
            *(uint4*)((char*)As + sw) = *(const uint4*)(Ag + (size_t)r * D + k0 + c * 8);
            *(uint4*)((char*)Bs + sw) = *(const uint4*)(Bg + (size_t)r * D + k0 + c * 8);
        }
        __syncthreads();
#pragma unroll
        for (int kk = 0; kk < 4; kk++) {      // 4 x k16 per 64-chunk
            uint32_t a[4][4];
#pragma unroll
            for (int mt = 0; mt < 4; mt++) {
                int m   = lane >> 3;
                int row = wm * 64 + mt * 16 + ((m & 1) << 3) + (lane & 7);
                int cc  = (kk << 1) + (m >> 1);
                unsigned addr = aBase + row * 128 + ((cc ^ (row & 7)) << 4);
                asm volatile("ldmatrix.sync.aligned.m8n8.x4.shared.b16 {%0,%1,%2,%3}, [%4];"
                             : "=r"(a[mt][0]), "=r"(a[mt][1]), "=r"(a[mt][2]), "=r"(a[mt][3])
                             : "r"(addr));
            }
            uint32_t b[4][2];
#pragma unroll
            for (int np = 0; np < 2; np++) {  // each x4 covers two n8 tiles
                int m   = lane >> 3;
                int row = wn * 32 + np * 16 + ((m >> 1) << 3) + (lane & 7);
                int cc  = (kk << 1) + (m & 1);
                unsigned addr = bBase + row * 128 + ((cc ^ (row & 7)) << 4);
                uint32_t r0, r1, r2, r3;
                asm volatile("ldmatrix.sync.aligned.m8n8.x4.shared.b16 {%0,%1,%2,%3}, [%4];"
                             : "=r"(r0), "=r"(r1), "=r"(r2), "=r"(r3) : "r"(addr));
                b[np * 2 + 0][0] = r0; b[np * 2 + 0][1] = r1;
                b[np * 2 + 1][0] = r2; b[np * 2 + 1][1] = r3;
            }
#pragma unroll
            for (int mt = 0; mt < 4; mt++)
#pragma unroll
                for (int nt = 0; nt < 4; nt++)
                    asm volatile(
                        "mma.sync.aligned.m16n8k16.row.col.f32.bf16.bf16.f32 "
                        "{%0,%1,%2,%3}, {%4,%5,%6,%7}, {%8,%9}, {%0,%1,%2,%3};"
                        : "+f"(acc[mt][nt][0]), "+f"(acc[mt][nt][1]),
                          "+f"(acc[mt][nt][2]), "+f"(acc[mt][nt][3])
                        : "r"(a[mt][0]), "r"(a[mt][1]), "r"(a[mt][2]), "r"(a[mt][3]),
                          "r"(b[nt][0]), "r"(b[nt][1]));
        }
        __syncthreads();
    }

    // epilogue: S = mnorm[n] - 2*acc
    int g = lane >> 2, tg = lane & 3;
#pragma unroll
    for (int mt = 0; mt < 4; mt++) {
#pragma unroll
        for (int nt = 0; nt < 4; nt++) {
            int row0 = by * 128 + wm * 64 + mt * 16 + g;
            int col0 = bx * 128 + wn * 32 + nt * 8 + tg * 2;
            float bn0 = mn[col0], bn1 = mn[col0 + 1];
            S[(size_t)row0 * NMEM + col0]           = bn0 - 2.f * acc[mt][nt][0];
            S[(size_t)row0 * NMEM + col0 + 1]       = bn1 - 2.f * acc[mt][nt][1];
            S[(size_t)(row0 + 8) * NMEM + col0]     = bn0 - 2.f * acc[mt][nt][2];
            S[(size_t)(row0 + 8) * NMEM + col0 + 1] = bn1 - 2.f * acc[mt][nt][3];
        }
    }
}

// ---------------------------------------------------------------------------
// Generic fp32 GEMM (NT): C[m,n] = act( alpha*sum_k A[m,k]*B[n,k] + bias[n]
//                                       + resid[m,n] ), optional A row gather.
// ---------------------------------------------------------------------------
__global__ __launch_bounds__(256, 2)
void gemm_nt_kernel(const float* __restrict__ A,
                    const float* __restrict__ Bm,
                    const float* __restrict__ bias,
                    const float* __restrict__ resid,
                    const int*   __restrict__ gidx,
                    float* __restrict__ C,
                    int N, int K, float alpha, int leaky)
{
    __shared__ float As[16][129];
    __shared__ float Bs[16][129];
    const int tid = threadIdx.x;
    const int bx = blockIdx.x, by = blockIdx.y;
    const int rbase = tid >> 4;
    const int cbase = tid & 15;

    float acc[8][8];
#pragma unroll
    for (int i = 0; i < 8; i++)
#pragma unroll
        for (int j = 0; j < 8; j++) acc[i][j] = 0.f;

    for (int k0 = 0; k0 < K; k0 += 16) {
        for (int l = tid; l < 512; l += 256) {
            int r = l >> 2, c4 = l & 3;
            int arow = by * 128 + r;
            if (gidx) arow = gidx[arow];
            float4 av = *(const float4*)(A + (size_t)arow * K + k0 + c4 * 4);
            As[c4 * 4 + 0][r] = av.x; As[c4 * 4 + 1][r] = av.y;
            As[c4 * 4 + 2][r] = av.z; As[c4 * 4 + 3][r] = av.w;
            int brow = bx * 128 + r;
            float4 bv = *(const float4*)(Bm + (size_t)brow * K + k0 + c4 * 4);
            Bs[c4 * 4 + 0][r] = bv.x; Bs[c4 * 4 + 1][r] = bv.y;
            Bs[c4 * 4 + 2][r] = bv.z; Bs[c4 * 4 + 3][r] = bv.w;
        }
        __syncthreads();
#pragma unroll
        for (int kk = 0; kk < 16; kk++) {
            float a[8], b[8];
#pragma unroll
            for (int i = 0; i < 8; i++) a[i] = As[kk][rbase + i * 16];
#pragma unroll
            for (int j = 0; j < 8; j++) b[j] = Bs[kk][cbase + j * 16];
#pragma unroll
            for (int i = 0; i < 8; i++)
#pragma unroll
                for (int j = 0; j < 8; j++)
                    acc[i][j] = fmaf(a[i], b[j], acc[i][j]);
        }
        __syncthreads();
    }

#pragma unroll
    for (int i = 0; i < 8; i++) {
        int row = by * 128 + rbase + i * 16;
#pragma unroll
        for (int j = 0; j < 8; j++) {
            int col = bx * 128 + cbase + j * 16;
            float v = alpha * acc[i][j];
            if (bias)  v += bias[col];
            if (resid) v += resid[(size_t)row * N + col];
            if (leaky) v = v > 0.f ? v : 0.01f * v;
            C[(size_t)row * N + col] = v;
        }
    }
}

// ---------------------------------------------------------------------------
// Top-K insertion helper
// ---------------------------------------------------------------------------
template <int T>
__device__ __forceinline__ void tk_insert(float v, int idx, float* bv, int* bi)
{
    if (v < bv[T - 1]) {
        float cv = v; int ci = idx;
#pragma unroll
        for (int t = 0; t < T; t++) {
            if (cv < bv[t]) {
                float tv = bv[t]; int ti = bi[t];
                bv[t] = cv; bi[t] = ci;
                cv = tv; ci = ti;
            }
        }
    }
}

// Per-row top-16 smallest over s[row, :]. One block (256 thr) per row.
__global__ void topk16_kernel(const float* __restrict__ s, int* __restrict__ C)
{
    int row = blockIdx.x, tid = threadIdx.x;
    const float4* sr = (const float4*)(s + (size_t)row * NMEM);
    float bv[TOPC]; int bi[TOPC];
#pragma unroll
    for (int t = 0; t < TOPC; t++) { bv[t] = 3.402823466e38f; bi[t] = 0; }

    for (int j = tid; j < NMEM / 4; j += 256) {
        float4 v = sr[j];
        int base = 4 * j;
        tk_insert<TOPC>(v.x, base + 0, bv, bi);
        tk_insert<TOPC>(v.y, base + 1, bv, bi);
        tk_insert<TOPC>(v.z, base + 2, bv, bi);
        tk_insert<TOPC>(v.w, base + 3, bv, bi);
    }

    __shared__ float sv[256 * TOPC];
    __shared__ int   si[256 * TOPC];
#pragma unroll
    for (int t = 0; t < TOPC; t++) { sv[tid * TOPC + t] = bv[t]; si[tid * TOPC + t] = bi[t]; }
    __syncthreads();

    if (tid < 32) {
        for (int k = 1; k < 8; k++) {
            int base = (tid + 32 * k) * TOPC;
            for (int t = 0; t < TOPC; t++) tk_insert<TOPC>(sv[base + t], si[base + t], bv, bi);
        }
#pragma unroll
        for (int t = 0; t < TOPC; t++) { sv[tid * TOPC + t] = bv[t]; si[tid * TOPC + t] = bi[t]; }
    }
    __syncthreads();

    if (tid == 0) {
        for (int k = 1; k < 32; k++) {
            int base = k * TOPC;
            for (int t = 0; t < TOPC; t++) tk_insert<TOPC>(sv[base + t], si[base + t], bv, bi);
        }
#pragma unroll
        for (int t = 0; t < TOPC; t++) C[row * TOPC + t] = bi[t];
    }
}

// ---------------------------------------------------------------------------
// Exact fp32 rescore of 16 candidates -> final top-10 indices.
// One block (512 thr = 16 warps) per query; warp w handles candidate w.
// ---------------------------------------------------------------------------
__global__ void rescore_kernel(const float* __restrict__ Q,
                               const float* __restrict__ M,
                               const float* __restrict__ mn,
                               const int*   __restrict__ C,
                               int* __restrict__ I)
{
    int b = blockIdx.x;
    int w = threadIdx.x >> 5, lane = threadIdx.x & 31;
    __shared__ float sv[TOPC];
    __shared__ int   si[TOPC];

    int c = C[b * TOPC + w];
    const float* qr = Q + (size_t)b * D;
    const float* mr = M + (size_t)c * D;
    float dot = 0.f;
#pragma unroll
    for (int i = 0; i < D / 32; i++)
        dot = fmaf(qr[lane + i * 32], mr[lane + i * 32], dot);
#pragma unroll
    for (int o = 16; o; o >>= 1) dot += __shfl_xor_sync(0xFFFFFFFFu, dot, o);
    if (lane == 0) { sv[w] = mn[c] - 2.f * dot; si[w] = c; }
    __syncthreads();

    if (threadIdx.x == 0) {
        float bv[TOPN]; int bi[TOPN];
#pragma unroll
        for (int t = 0; t < TOPN; t++) { bv[t] = 3.402823466e38f; bi[t] = 0; }
        for (int k = 0; k < TOPC; k++) tk_insert<TOPN>(sv[k], si[k], bv, bi);
#pragma unroll
        for (int t = 0; t < TOPN; t++) I[b * TOPN + t] = bi[t];
    }
}

// ---------------------------------------------------------------------------
// Attention: query seq-len 1, 10 keys, 8 heads x hd=64.
// ---------------------------------------------------------------------------
__global__ void attn_kernel(const float* __restrict__ qh,
                            const float* __restrict__ kh,
                            const float* __restrict__ vh,
                            float* __restrict__ ctx)
{
    int b = blockIdx.x;
    int h = threadIdx.x >> 5, lane = threadIdx.x & 31;
    const float* qp = qh + (size_t)b * D + h * 64;
    float q0 = qp[lane], q1 = qp[lane + 32];

    float sc[TOPN];
#pragma unroll
    for (int n = 0; n < TOPN; n++) {
        const float* kp = kh + ((size_t)b * TOPN + n) * D + h * 64;
        float p = q0 * kp[lane] + q1 * kp[lane + 32];
#pragma unroll
        for (int o = 16; o; o >>= 1) p += __shfl_xor_sync(0xFFFFFFFFu, p, o);
        sc[n] = p * 0.125f;
    }
    float mx = sc[0];
#pragma unroll
    for (int n = 1; n < TOPN; n++) mx = fmaxf(mx, sc[n]);
    float den = 0.f;
#pragma unroll
    for (int n = 0; n < TOPN; n++) { sc[n] = expf(sc[n] - mx); den += sc[n]; }
    float inv = 1.f / den;

    float c0 = 0.f, c1 = 0.f;
#pragma unroll
    for (int n = 0; n < TOPN; n++) {
        const float* vp = vh + ((size_t)b * TOPN + n) * D + h * 64;
        float a = sc[n] * inv;
        c0 = fmaf(a, vp[lane], c0);
        c1 = fmaf(a, vp[lane + 32], c1);
    }
    ctx[(size_t)b * D + h * 64 + lane]      = c0;
    ctx[(size_t)b * D + h * 64 + lane + 32] = c1;
}

// ---------------------------------------------------------------------------
// LayerNorm over last dim (512). One block (128 thr) per row.
// ---------------------------------------------------------------------------
__global__ void ln_kernel(const float* __restrict__ y,
                          const float* __restrict__ g,
                          const float* __restrict__ b,
                          float* __restrict__ out)
{
    int row = blockIdx.x, tid = threadIdx.x;
    const float* yr = y + (size_t)row * D;
    float v[4];
#pragma unroll
    for (int i = 0; i < 4; i++) v[i] = yr[tid + i * 128];

    __shared__ float red[4];
    float s = v[0] + v[1] + v[2] + v[3];
#pragma unroll
    for (int o = 16; o; o >>= 1) s += __shfl_xor_sync(0xFFFFFFFFu, s, o);
    if ((tid & 31) == 0) red[tid >> 5] = s;
    __syncthreads();
    float mu = (red[0] + red[1] + red[2] + red[3]) * (1.f / D);

    float s2 = 0.f;
#pragma unroll
    for (int i = 0; i < 4; i++) { float d = v[i] - mu; s2 += d * d; }
#pragma unroll
    for (int o = 16; o; o >>= 1) s2 += __shfl_xor_sync(0xFFFFFFFFu, s2, o);
    __syncthreads();
    if ((tid & 31) == 0) red[tid >> 5] = s2;
    __syncthreads();
    float var = (red[0] + red[1] + red[2] + red[3]) * (1.f / D);
    float invs = rsqrtf(var + 1e-5f);

#pragma unroll
    for (int i = 0; i < 4; i++) {
        int c = tid + i * 128;
        out[(size_t)row * D + c] = (v[i] - mu) * invs * g[c] + b[c];
    }
}

// ---------------------------------------------------------------------------
// Host launcher
// ---------------------------------------------------------------------------
extern "C" void kernel_launch(void* const* d_in, const int* in_sizes, int n_in,
                              void* d_out, int out_size)
{
    (void)n_in; (void)out_size;
    const float* visit = (const float*)d_in[0];
    const float* Epat  = (const float*)d_in[1];
    const float* Emed  = (const float*)d_in[2];

    const float *Wq, *bq, *Wk, *bk, *Wv, *bv;
    if (in_sizes[4] == D) {
        Wq = (const float*)d_in[3]; bq = (const float*)d_in[4];
        Wk = (const float*)d_in[5]; bk = (const float*)d_in[6];
        Wv = (const float*)d_in[7]; bv = (const float*)d_in[8];
    } else {
        Wq = (const float*)d_in[3]; Wk = (const float*)d_in[4]; Wv = (const float*)d_in[5];
        bq = (const float*)d_in[6]; bk = (const float*)d_in[7]; bv = (const float*)d_in[8];
    }
    const float* Wo  = (const float*)d_in[9];
    const float* bo  = (const float*)d_in[10];
    const float* W1  = (const float*)d_in[11];
    const float* b1  = (const float*)d_in[12];
    const float* W2  = (const float*)d_in[13];
    const float* b2  = (const float*)d_in[14];
    const float* g1  = (const float*)d_in[15];
    const float* be1 = (const float*)d_in[16];
    const float* g2  = (const float*)d_in[17];
    const float* be2 = (const float*)d_in[18];

    float *s, *mn, *qh, *kh, *vh, *ctx, *y, *x, *h1, *y2;
    int *C, *I;
    __nv_bfloat16 *qb, *mb;
    cudaGetSymbolAddress((void**)&s,   g_s);
    cudaGetSymbolAddress((void**)&mn,  g_mnorm);
    cudaGetSymbolAddress((void**)&C,   g_C);
    cudaGetSymbolAddress((void**)&I,   g_I);
    cudaGetSymbolAddress((void**)&qb,  g_qb);
    cudaGetSymbolAddress((void**)&mb,  g_mb);
    cudaGetSymbolAddress((void**)&qh,  g_qh);
    cudaGetSymbolAddress((void**)&kh,  g_kh);
    cudaGetSymbolAddress((void**)&vh,  g_vh);
    cudaGetSymbolAddress((void**)&ctx, g_ctx);
    cudaGetSymbolAddress((void**)&y,   g_y);
    cudaGetSymbolAddress((void**)&x,   g_x);
    cudaGetSymbolAddress((void**)&h1,  g_h1);
    cudaGetSymbolAddress((void**)&y2,  g_y2);

    // 0) bf16 copies of Q and M
    cvt_bf16_kernel<<<(BQ * D / 4 + 255) / 256, 256>>>(visit, qb, BQ * D / 4);
    cvt_bf16_kernel<<<(NMEM * D / 4 + 255) / 256, 256>>>(Epat, mb, NMEM * D / 4);

    // 1) ||M||^2 (exact fp32)
    mnorm_kernel<<<NMEM / 8, 256>>>(Epat, mn);

    // 2) approx s = ||M||^2 - 2 * Q @ M^T via bf16 tensor cores
    dist_mma_kernel<<<dim3(NMEM / 128, BQ / 128), 256>>>(qb, mb, mn, s);

    // 3) approx top-16 candidates per row
    topk16_kernel<<<BQ, 256>>>(s, C);

    // 4) exact fp32 rescore -> final top-10
    rescore_kernel<<<BQ, 512>>>(visit, Epat, mn, C, I);

    // 5) projections (fp32 exact)
    gemm_nt_kernel<<<dim3(D / 128, BQ / 128), 256>>>(
        visit, Wq, bq, nullptr, nullptr, qh, D, D, 1.f, 0);
    gemm_nt_kernel<<<dim3(D / 128, (BQ * TOPN) / 128), 256>>>(
        Epat, Wk, bk, nullptr, I, kh, D, D, 1.f, 0);
    gemm_nt_kernel<<<dim3(D / 128, (BQ * TOPN) / 128), 256>>>(
        Emed, Wv, bv, nullptr, I, vh, D, D, 1.f, 0);

    // 6) attention
    attn_kernel<<<BQ, 256>>>(qh, kh, vh, ctx);

    // 7) y = ctx @ Wo^T + bo + visit ; x = LN1(y)
    gemm_nt_kernel<<<dim3(D / 128, BQ / 128), 256>>>(
        ctx, Wo, bo, visit, nullptr, y, D, D, 1.f, 0);
    ln_kernel<<<BQ, 128>>>(y, g1, be1, x);

    // 8) FFN + LN2
    gemm_nt_kernel<<<dim3(D / 128, BQ / 128), 256>>>(
        x, W1, b1, nullptr, nullptr, h1, D, D, 1.f, 1);
    gemm_nt_kernel<<<dim3(D / 128, BQ / 128), 256>>>(
        h1, W2, b2, x, nullptr, y2, D, D, 1.f, 0);
    ln_kernel<<<BQ, 128>>>(y2, g2, be2, (float*)d_out);
}